// round 1
// baseline (speedup 1.0000x reference)
#include <cuda_runtime.h>
#include <cuda_bf16.h>

#define D_MODEL 2048
#define HIDDEN 1024
#define NUM_EXPERTS 8
#define TOKENS_PER_EXPERT 2048
#define TOTAL_TOKENS 16384

// Scratch: ug = x @ Wug^T  (16384 x 2048), h = silu(gate)*up (16384 x 1024)
__device__ float g_ug[(size_t)TOTAL_TOKENS * 2 * HIDDEN];
__device__ float g_h[(size_t)TOTAL_TOKENS * HIDDEN];

// C[M,N] = A[M,K] @ B[N,K]^T   (both row-major, per-expert base offsets)
// BM=BN=128, BK=16, 256 threads, 8x8 per-thread micro-tile.
template <int BM, int BN, int BK, int TM, int TN>
__global__ __launch_bounds__(256, 2)
void sgemm_abt_kernel(const float* __restrict__ A,
                      const float* __restrict__ B,
                      float* __restrict__ C,
                      int lda, int ldb, int ldc, int K,
                      long a_estride, long b_estride, long c_estride)
{
    const int e = blockIdx.z;
    const float* Ae = A + (long)e * a_estride;
    const float* Be = B + (long)e * b_estride;
    float*       Ce = C + (long)e * c_estride;

    __shared__ float As[BK][BM];
    __shared__ float Bs[BK][BN];

    const int m0 = blockIdx.y * BM;
    const int n0 = blockIdx.x * BN;

    const int tid = threadIdx.x;             // 0..255
    const int tx  = tid % (BN / TN);         // 0..15 (n)
    const int ty  = tid / (BN / TN);         // 0..15 (m)

    // Tile-load mapping: 256 threads, float4 along K. 64 rows per pass.
    const int lrow = tid / (BK / 4);         // 0..63
    const int lcol = (tid % (BK / 4)) * 4;   // 0,4,8,12

    float acc[TM][TN];
    #pragma unroll
    for (int i = 0; i < TM; i++)
        #pragma unroll
        for (int j = 0; j < TN; j++) acc[i][j] = 0.0f;

    for (int k0 = 0; k0 < K; k0 += BK) {
        // A tile: BM x BK (store transposed -> As[k][m])
        #pragma unroll
        for (int r = 0; r < BM; r += 64) {
            float4 v = *reinterpret_cast<const float4*>(
                &Ae[(long)(m0 + lrow + r) * lda + (k0 + lcol)]);
            As[lcol + 0][lrow + r] = v.x;
            As[lcol + 1][lrow + r] = v.y;
            As[lcol + 2][lrow + r] = v.z;
            As[lcol + 3][lrow + r] = v.w;
        }
        // B tile: BN x BK (store transposed -> Bs[k][n])
        #pragma unroll
        for (int r = 0; r < BN; r += 64) {
            float4 v = *reinterpret_cast<const float4*>(
                &Be[(long)(n0 + lrow + r) * ldb + (k0 + lcol)]);
            Bs[lcol + 0][lrow + r] = v.x;
            Bs[lcol + 1][lrow + r] = v.y;
            Bs[lcol + 2][lrow + r] = v.z;
            Bs[lcol + 3][lrow + r] = v.w;
        }
        __syncthreads();

        #pragma unroll
        for (int k = 0; k < BK; k++) {
            float ar[TM], br[TN];
            float4 a0 = *reinterpret_cast<const float4*>(&As[k][ty * TM]);
            float4 a1 = *reinterpret_cast<const float4*>(&As[k][ty * TM + 4]);
            float4 b0 = *reinterpret_cast<const float4*>(&Bs[k][tx * TN]);
            float4 b1 = *reinterpret_cast<const float4*>(&Bs[k][tx * TN + 4]);
            ar[0]=a0.x; ar[1]=a0.y; ar[2]=a0.z; ar[3]=a0.w;
            ar[4]=a1.x; ar[5]=a1.y; ar[6]=a1.z; ar[7]=a1.w;
            br[0]=b0.x; br[1]=b0.y; br[2]=b0.z; br[3]=b0.w;
            br[4]=b1.x; br[5]=b1.y; br[6]=b1.z; br[7]=b1.w;
            #pragma unroll
            for (int i = 0; i < TM; i++)
                #pragma unroll
                for (int j = 0; j < TN; j++)
                    acc[i][j] = fmaf(ar[i], br[j], acc[i][j]);
        }
        __syncthreads();
    }

    // Store C (all dims divide evenly; no guards needed)
    #pragma unroll
    for (int i = 0; i < TM; i++) {
        float4 c0, c1;
        c0.x = acc[i][0]; c0.y = acc[i][1]; c0.z = acc[i][2]; c0.w = acc[i][3];
        c1.x = acc[i][4]; c1.y = acc[i][5]; c1.z = acc[i][6]; c1.w = acc[i][7];
        long row = (long)(m0 + ty * TM + i);
        *reinterpret_cast<float4*>(&Ce[row * ldc + n0 + tx * TN + 0]) = c0;
        *reinterpret_cast<float4*>(&Ce[row * ldc + n0 + tx * TN + 4]) = c1;
    }
}

// h[t, j] = silu(ug[t, j]) * ug[t, HIDDEN + j]
__global__ void silu_mul_kernel(const float* __restrict__ ug, float* __restrict__ h)
{
    long idx = (long)blockIdx.x * blockDim.x + threadIdx.x;  // over T*HIDDEN/4
    long t = idx / (HIDDEN / 4);
    long j = idx % (HIDDEN / 4);

    const float4 g = reinterpret_cast<const float4*>(ug + t * (2 * HIDDEN))[j];
    const float4 u = reinterpret_cast<const float4*>(ug + t * (2 * HIDDEN) + HIDDEN)[j];
    float4 r;
    r.x = (g.x / (1.0f + __expf(-g.x))) * u.x;
    r.y = (g.y / (1.0f + __expf(-g.y))) * u.y;
    r.z = (g.z / (1.0f + __expf(-g.z))) * u.z;
    r.w = (g.w / (1.0f + __expf(-g.w))) * u.w;
    reinterpret_cast<float4*>(h + t * HIDDEN)[j] = r;
}

extern "C" void kernel_launch(void* const* d_in, const int* in_sizes, int n_in,
                              void* d_out, int out_size)
{
    const float* x        = (const float*)d_in[0];  // [16384, 2048]
    const float* w_upgate = (const float*)d_in[1];  // [16384, 2048] = [E, 2H, D]
    const float* w_down   = (const float*)d_in[2];  // [2048, 8192]  = [D, E*H]
    float* out = (float*)d_out;                     // [16384, 2048]

    float* ug; cudaGetSymbolAddress((void**)&ug, g_ug);
    float* h;  cudaGetSymbolAddress((void**)&h,  g_h);

    constexpr int BM = 128, BN = 128, BK = 16, TM = 8, TN = 8;

    // GEMM 1: ug[e-tokens, 2H] = x_e @ Wug_e^T   (M=2048/e, N=2048, K=2048)
    {
        dim3 grid(2 * HIDDEN / BN, TOKENS_PER_EXPERT / BM, NUM_EXPERTS);
        sgemm_abt_kernel<BM, BN, BK, TM, TN><<<grid, 256>>>(
            x, w_upgate, ug,
            /*lda=*/D_MODEL, /*ldb=*/D_MODEL, /*ldc=*/2 * HIDDEN, /*K=*/D_MODEL,
            /*a_estride=*/(long)TOKENS_PER_EXPERT * D_MODEL,
            /*b_estride=*/(long)2 * HIDDEN * D_MODEL,
            /*c_estride=*/(long)TOKENS_PER_EXPERT * 2 * HIDDEN);
    }

    // silu(gate) * up
    {
        long n4 = (long)TOTAL_TOKENS * HIDDEN / 4;
        silu_mul_kernel<<<(unsigned)(n4 / 256), 256>>>(ug, h);
    }

    // GEMM 2: out[e-tokens, D] = h_e @ Wd_e^T   (M=2048/e, N=2048, K=1024)
    // Wd_e[n][k] = w_down[n * 8192 + e*1024 + k]
    {
        dim3 grid(D_MODEL / BN, TOKENS_PER_EXPERT / BM, NUM_EXPERTS);
        sgemm_abt_kernel<BM, BN, BK, TM, TN><<<grid, 256>>>(
            h, w_down, out,
            /*lda=*/HIDDEN, /*ldb=*/NUM_EXPERTS * HIDDEN, /*ldc=*/D_MODEL, /*K=*/HIDDEN,
            /*a_estride=*/(long)TOKENS_PER_EXPERT * HIDDEN,
            /*b_estride=*/(long)HIDDEN,
            /*c_estride=*/(long)TOKENS_PER_EXPERT * D_MODEL);
    }
}

// round 3
// speedup vs baseline: 2.6346x; 2.6346x over previous
#include <cuda_runtime.h>
#include <cuda_bf16.h>
#include <cstdint>

#define D_MODEL 2048
#define HIDDEN 1024
#define NUM_EXPERTS 8
#define TPE 2048
#define TOTAL_TOKENS 16384

// fp32 scratch for h = silu(gate)*up : [16384, 1024]
__device__ float g_h[(size_t)TOTAL_TOKENS * HIDDEN];

// ---------------- helpers ----------------
__device__ __forceinline__ uint32_t sw(uint32_t off) {
    // rows are 64B (32 bf16); XOR bits[5:4] with bits[8:7] -> conflict-free frags
    return off ^ ((off >> 3) & 0x30);
}

__device__ __forceinline__ void mma_bf16(float* c, const uint32_t* a, const uint32_t* b) {
    asm volatile(
        "mma.sync.aligned.m16n8k16.row.col.f32.bf16.bf16.f32 "
        "{%0,%1,%2,%3}, {%4,%5,%6,%7}, {%8,%9}, {%0,%1,%2,%3};"
        : "+f"(c[0]), "+f"(c[1]), "+f"(c[2]), "+f"(c[3])
        : "r"(a[0]), "r"(a[1]), "r"(a[2]), "r"(a[3]), "r"(b[0]), "r"(b[1]));
}

__device__ __forceinline__ uint32_t pack_bf16x2(float lo_f, float hi_f) {
    __nv_bfloat162 p(__float2bfloat16(lo_f), __float2bfloat16(hi_f));
    return *reinterpret_cast<uint32_t*>(&p);
}

// split float4 (4 consecutive K values) into hi/lo packed pairs
__device__ __forceinline__ void split4(float4 v, uint2& hv, uint2& lv) {
    float hx = __bfloat162float(__float2bfloat16(v.x));
    float hy = __bfloat162float(__float2bfloat16(v.y));
    float hz = __bfloat162float(__float2bfloat16(v.z));
    float hw = __bfloat162float(__float2bfloat16(v.w));
    hv.x = pack_bf16x2(v.x, v.y);          // rounds again, same result
    hv.y = pack_bf16x2(v.z, v.w);
    lv.x = pack_bf16x2(v.x - hx, v.y - hy);
    lv.y = pack_bf16x2(v.z - hz, v.w - hw);
}

// SMEM stage layout (bytes): Ahi 0, Alo 8192, Bhi 16384, Blo 24576; stage = 32768
#define TILE8K 8192
#define STAGE 32768

// store one 128x32 fp32 tile (already in regs as 4 float4/thread) as bf16 hi/lo
__device__ __forceinline__ void sts_tile(char* dhi, char* dlo, const float4* r, int tid) {
    #pragma unroll
    for (int it = 0; it < 4; it++) {
        int idx = it * 256 + tid;
        int row = idx >> 3;            // 0..127
        int c4  = idx & 7;             // float4 within 32-col row
        uint2 hv, lv;
        split4(r[it], hv, lv);
        uint32_t off = sw((uint32_t)(row * 64 + c4 * 8));
        *reinterpret_cast<uint2*>(dhi + off) = hv;
        *reinterpret_cast<uint2*>(dlo + off) = lv;
    }
}

// compute one 32-K chunk: 3 passes (hi*hi, hi*lo, lo*hi), 2 k16 steps
__device__ __forceinline__ void compute_chunk(const char* st, float acc[4][4][4],
                                              int g, int tg, int mw, int nw) {
    const char* Ahi = st;
    const char* Alo = st + TILE8K;
    const char* Bhi = st + 2 * TILE8K;
    const char* Blo = st + 3 * TILE8K;

    #pragma unroll
    for (int ks = 0; ks < 2; ks++) {
        #pragma unroll
        for (int p = 0; p < 3; p++) {
            const char* Ap = (p == 2) ? Alo : Ahi;
            const char* Bp = (p == 1) ? Blo : Bhi;
            uint32_t a[4][4], b[4][2];
            #pragma unroll
            for (int mt = 0; mt < 4; mt++) {
                int r0 = mw * 64 + mt * 16 + g;
                uint32_t base = (uint32_t)(ks * 32 + tg * 4);
                a[mt][0] = *reinterpret_cast<const uint32_t*>(Ap + sw(r0 * 64 + base));
                a[mt][1] = *reinterpret_cast<const uint32_t*>(Ap + sw((r0 + 8) * 64 + base));
                a[mt][2] = *reinterpret_cast<const uint32_t*>(Ap + sw(r0 * 64 + base + 16));
                a[mt][3] = *reinterpret_cast<const uint32_t*>(Ap + sw((r0 + 8) * 64 + base + 16));
            }
            #pragma unroll
            for (int nt = 0; nt < 4; nt++) {
                int br = nw * 32 + nt * 8 + g;
                uint32_t base = (uint32_t)(ks * 32 + tg * 4);
                b[nt][0] = *reinterpret_cast<const uint32_t*>(Bp + sw(br * 64 + base));
                b[nt][1] = *reinterpret_cast<const uint32_t*>(Bp + sw(br * 64 + base + 16));
            }
            #pragma unroll
            for (int mt = 0; mt < 4; mt++)
                #pragma unroll
                for (int nt = 0; nt < 4; nt++)
                    mma_bf16(acc[mt][nt], a[mt], b[nt]);
        }
    }
}

__device__ __forceinline__ float silu(float x) {
    return x / (1.0f + __expf(-x));
}

// ---------------- kernel 1: h = silu(x@Wg^T) * (x@Wu^T), fused ----------------
// CTA: 128 tokens x 64 h-cols. B-tile (128 rows) interleaves gate/up per 16 rows
// so every warp (64x32 tile) holds matching gate/up columns for in-register fusion.
__global__ __launch_bounds__(256, 1)
void moe_upgate_kernel(const float* __restrict__ x,
                       const float* __restrict__ w_upgate,
                       float* __restrict__ h_out)
{
    extern __shared__ char smem[];

    const int tid = threadIdx.x;
    const int lane = tid & 31, warp = tid >> 5;
    const int g = lane >> 2, tg = lane & 3;
    const int nw = warp & 3, mw = warp >> 2;

    const int e = blockIdx.z;
    const int m0 = blockIdx.y * 128;
    const int n0 = blockIdx.x * 64;

    const float* A  = x + (long)e * TPE * D_MODEL + (long)m0 * D_MODEL;
    const float* Bg = w_upgate + (long)e * 2 * HIDDEN * D_MODEL;
    const float* Bu = Bg + (long)HIDDEN * D_MODEL;

    // per-thread load coords
    const int lrow = tid >> 3;      // += 32 per iter
    const int lc4  = tid & 7;

    float acc[4][4][4];
    #pragma unroll
    for (int i = 0; i < 4; i++)
        #pragma unroll
        for (int j = 0; j < 4; j++)
            #pragma unroll
            for (int k = 0; k < 4; k++) acc[i][j][k] = 0.0f;

    float4 ra[4], rb[4];

    auto ldg = [&](int k0) {
        #pragma unroll
        for (int it = 0; it < 4; it++) {
            int r = it * 32 + lrow;
            ra[it] = *reinterpret_cast<const float4*>(A + (long)r * D_MODEL + k0 + lc4 * 4);
            // B~ row r -> warp-chunk w=r>>5 (16 cols each), s: 0=gate 1=up
            int w = r >> 5, s = (r >> 4) & 1, rr = (r & 15) + w * 16;
            const float* bp = s ? Bu : Bg;
            rb[it] = *reinterpret_cast<const float4*>(bp + (long)(n0 + rr) * D_MODEL + k0 + lc4 * 4);
        }
    };

    const int NCH = D_MODEL / 32;   // 64
    ldg(0);
    sts_tile(smem, smem + TILE8K, ra, tid);
    sts_tile(smem + 2 * TILE8K, smem + 3 * TILE8K, rb, tid);

    for (int c = 0; c < NCH; c++) {
        __syncthreads();
        if (c + 1 < NCH) ldg((c + 1) * 32);
        compute_chunk(smem + (c & 1) * STAGE, acc, g, tg, mw, nw);
        if (c + 1 < NCH) {
            char* st = smem + ((c + 1) & 1) * STAGE;
            sts_tile(st, st + TILE8K, ra, tid);
            sts_tile(st + 2 * TILE8K, st + 3 * TILE8K, rb, tid);
        }
    }

    // epilogue: nt 0,1 = gate cols, nt 2,3 = matching up cols
    #pragma unroll
    for (int mt = 0; mt < 4; mt++) {
        long row0 = (long)e * TPE + m0 + mw * 64 + mt * 16 + g;
        #pragma unroll
        for (int nt = 0; nt < 2; nt++) {
            int col = n0 + nw * 16 + nt * 8 + tg * 2;
            float2 v0, v1;
            v0.x = silu(acc[mt][nt][0]) * acc[mt][nt + 2][0];
            v0.y = silu(acc[mt][nt][1]) * acc[mt][nt + 2][1];
            v1.x = silu(acc[mt][nt][2]) * acc[mt][nt + 2][2];
            v1.y = silu(acc[mt][nt][3]) * acc[mt][nt + 2][3];
            *reinterpret_cast<float2*>(g_h + row0 * HIDDEN + col) = v0;
            *reinterpret_cast<float2*>(g_h + (row0 + 8) * HIDDEN + col) = v1;
        }
    }
}

// ---------------- kernel 2: out = h @ Wd^T ----------------
__global__ __launch_bounds__(256, 1)
void moe_down_kernel(const float* __restrict__ w_down,
                     float* __restrict__ out)
{
    extern __shared__ char smem[];

    const int tid = threadIdx.x;
    const int lane = tid & 31, warp = tid >> 5;
    const int g = lane >> 2, tg = lane & 3;
    const int nw = warp & 3, mw = warp >> 2;

    const int e = blockIdx.z;
    const int m0 = blockIdx.y * 128;
    const int n0 = blockIdx.x * 128;

    const float* A = g_h + (long)e * TPE * HIDDEN + (long)m0 * HIDDEN;
    const float* B = w_down + (long)n0 * (NUM_EXPERTS * HIDDEN) + (long)e * HIDDEN;

    const int lrow = tid >> 3;
    const int lc4  = tid & 7;

    float acc[4][4][4];
    #pragma unroll
    for (int i = 0; i < 4; i++)
        #pragma unroll
        for (int j = 0; j < 4; j++)
            #pragma unroll
            for (int k = 0; k < 4; k++) acc[i][j][k] = 0.0f;

    float4 ra[4], rb[4];

    auto ldg = [&](int k0) {
        #pragma unroll
        for (int it = 0; it < 4; it++) {
            int r = it * 32 + lrow;
            ra[it] = *reinterpret_cast<const float4*>(A + (long)r * HIDDEN + k0 + lc4 * 4);
            rb[it] = *reinterpret_cast<const float4*>(B + (long)r * (NUM_EXPERTS * HIDDEN) + k0 + lc4 * 4);
        }
    };

    const int NCH = HIDDEN / 32;    // 32
    ldg(0);
    sts_tile(smem, smem + TILE8K, ra, tid);
    sts_tile(smem + 2 * TILE8K, smem + 3 * TILE8K, rb, tid);

    for (int c = 0; c < NCH; c++) {
        __syncthreads();
        if (c + 1 < NCH) ldg((c + 1) * 32);
        compute_chunk(smem + (c & 1) * STAGE, acc, g, tg, mw, nw);
        if (c + 1 < NCH) {
            char* st = smem + ((c + 1) & 1) * STAGE;
            sts_tile(st, st + TILE8K, ra, tid);
            sts_tile(st + 2 * TILE8K, st + 3 * TILE8K, rb, tid);
        }
    }

    #pragma unroll
    for (int mt = 0; mt < 4; mt++) {
        long row0 = (long)e * TPE + m0 + mw * 64 + mt * 16 + g;
        #pragma unroll
        for (int nt = 0; nt < 4; nt++) {
            int col = n0 + nw * 32 + nt * 8 + tg * 2;
            float2 v0, v1;
            v0.x = acc[mt][nt][0]; v0.y = acc[mt][nt][1];
            v1.x = acc[mt][nt][2]; v1.y = acc[mt][nt][3];
            *reinterpret_cast<float2*>(out + row0 * D_MODEL + col) = v0;
            *reinterpret_cast<float2*>(out + (row0 + 8) * D_MODEL + col) = v1;
        }
    }
}

// ---------------- launch ----------------
extern "C" void kernel_launch(void* const* d_in, const int* in_sizes, int n_in,
                              void* d_out, int out_size)
{
    const float* x        = (const float*)d_in[0];  // [16384, 2048]
    const float* w_upgate = (const float*)d_in[1];  // [E*2H, D]
    const float* w_down   = (const float*)d_in[2];  // [D, E*H]
    float* out = (float*)d_out;

    static bool attr_set = false;
    if (!attr_set) {
        cudaFuncSetAttribute(moe_upgate_kernel,
                             cudaFuncAttributeMaxDynamicSharedMemorySize, 2 * STAGE);
        cudaFuncSetAttribute(moe_down_kernel,
                             cudaFuncAttributeMaxDynamicSharedMemorySize, 2 * STAGE);
        attr_set = true;
    }

    float* hptr;
    cudaGetSymbolAddress((void**)&hptr, g_h);

    {
        dim3 grid(HIDDEN / 64, TPE / 128, NUM_EXPERTS);   // (16,16,8)
        moe_upgate_kernel<<<grid, 256, 2 * STAGE>>>(x, w_upgate, hptr);
    }
    {
        dim3 grid(D_MODEL / 128, TPE / 128, NUM_EXPERTS); // (16,16,8)
        moe_down_kernel<<<grid, 256, 2 * STAGE>>>(w_down, out);
    }
}